// round 2
// baseline (speedup 1.0000x reference)
#include <cuda_runtime.h>
#include <math.h>

// Problem constants
constexpr int BB   = 8;     // batch
constexpr int NCLS = 2;     // n_classes
constexpr int NSP  = 8;     // n_space
constexpr int CH   = 64;    // channels
constexpr int HH   = 192;
constexpr int WW   = 192;
constexpr int HWSZ = HH * WW;   // 36864

// ---------------- device scratch (no runtime allocation allowed) ----------------
__device__ float g_space[BB * NCLS * NSP * HWSZ];   // [b][c][s][hw]  raw (unnormalized) space
__device__ float g_S[BB * NCLS * NSP];              // spatial sums per (b,c,s)
__device__ float g_P[BB * NSP * NCLS * CH * 9];     // correlation tensor [b][s][c][c'][k]
__device__ float g_tok2[BB * NCLS * CH];            // [b][c][d]
__device__ float g_wT[CH * CH * 9];                 // W_single transposed to [d][k][o]
__device__ float g_y[BB * CH * HWSZ];               // conv output pre-BN
__device__ float g_bnsum[CH];
__device__ float g_bnsq[CH];
__device__ float g_bna[CH];
__device__ float g_bnb[CH];

__device__ __forceinline__ float sigmoidf_(float x) {
    return 1.0f / (1.0f + __expf(-x));
}

// ---------------- kernel 0: zero accumulators ----------------
__global__ void k_zero() {
    int i = blockIdx.x * blockDim.x + threadIdx.x;
    if (i < BB * NSP * NCLS * CH * 9) g_P[i] = 0.f;
    if (i < BB * NCLS * NSP) g_S[i] = 0.f;
    if (i < BB * NCLS * CH) g_tok2[i] = 0.f;
    if (i < CH) { g_bnsum[i] = 0.f; g_bnsq[i] = 0.f; }
}

// ---------------- kernel 0b: transpose W_single (OIHW -> [d][k][o]) ----------------
__global__ void k_wT(const float* __restrict__ Ws) {
    int i = blockIdx.x * blockDim.x + threadIdx.x;
    if (i < CH * CH * 9) {
        int o = i / 576;
        int rem = i % 576;
        int d = rem / 9;
        int k = rem % 9;
        g_wT[d * 576 + k * 64 + o] = Ws[i];
    }
}

// ---------------- kernel 1: class_prob -> space channels + spatial sums ----------------
// grid (144, 16), block 256.  blockIdx.y = b*NCLS + c
__global__ void k_space(const float* __restrict__ cs, const float* __restrict__ Wcsp) {
    int bc = blockIdx.y;
    int p = blockIdx.x * 256 + threadIdx.x;       // exact: 144*256 == HWSZ
    int h = p / WW, w = p % WW;
    const float* base = cs + bc * HWSZ;

    float n[9];
#pragma unroll
    for (int dy = 0; dy < 3; dy++) {
#pragma unroll
        for (int dx = 0; dx < 3; dx++) {
            int gh = h + dy - 1, gw = w + dx - 1;
            float v = 0.f;
            if (gh >= 0 && gh < HH && gw >= 0 && gw < WW)
                v = sigmoidf_(base[gh * WW + gw]);
            n[dy * 3 + dx] = v;
        }
    }

    float sums[NSP];
    float ch0 = n[4];
    g_space[(bc * NSP + 0) * HWSZ + p] = ch0;
    sums[0] = ch0;
#pragma unroll
    for (int j = 0; j < 7; j++) {
        float z = 0.f;
#pragma unroll
        for (int k = 0; k < 9; k++) z += Wcsp[j * 9 + k] * n[k];
        float v = sigmoidf_(z);
        g_space[(bc * NSP + j + 1) * HWSZ + p] = v;
        sums[j + 1] = v;
    }

#pragma unroll
    for (int s = 0; s < NSP; s++) {
        float v = sums[s];
#pragma unroll
        for (int off = 16; off; off >>= 1)
            v += __shfl_down_sync(0xffffffffu, v, off);
        if ((threadIdx.x & 31) == 0) atomicAdd(&g_S[bc * NSP + s], v);
    }
}

// ---------------- kernel 2: P correlation ----------------
// grid (12 strips, 8 c'-groups, 8 b), block 128.
__device__ __forceinline__ void load_x_row(float (*s_x)[3][200], const float* __restrict__ xb,
                                           int grow, int tid) {
    int slot = ((grow % 3) + 3) % 3;
    bool rok = (grow >= 0 && grow < HH);
    for (int i = tid; i < 8 * 194; i += 128) {
        int cp = i / 194, cc = i % 194;
        int gcol = cc - 1;
        float v = 0.f;
        if (rok && gcol >= 0 && gcol < WW) v = xb[cp * HWSZ + grow * WW + gcol];
        s_x[cp][slot][cc] = v;
    }
}

__global__ __launch_bounds__(128) void k_P(const float* __restrict__ x) {
    __shared__ float s_x[8][3][200];   // [c'][slot][col+1]
    __shared__ float s_sp[16][192];    // [sc][col]

    int b = blockIdx.z, cgrp = blockIdx.y, strip = blockIdx.x;
    int r0 = strip * 16;
    int tid = threadIdx.x;
    int scg = tid >> 5;          // 0..3, handles 4 sc each
    int rem = tid & 31;
    int cpl = rem >> 2;          // 0..7 local c'
    int cch = rem & 3;           // 0..3 column chunk
    int col0 = cch * 48;

    float acc[4][9];
#pragma unroll
    for (int i = 0; i < 4; i++)
#pragma unroll
        for (int k = 0; k < 9; k++) acc[i][k] = 0.f;

    const float* xb = x + (b * CH + cgrp * 8) * HWSZ;

    load_x_row(s_x, xb, r0 - 1, tid);
    load_x_row(s_x, xb, r0, tid);

    for (int r = r0; r < r0 + 16; r++) {
        __syncthreads();
        load_x_row(s_x, xb, r + 1, tid);
        for (int i = tid; i < 16 * 192; i += 128) {
            int sc = i / 192, col = i % 192;
            int cc = sc >> 3, ss = sc & 7;
            s_sp[sc][col] = g_space[((b * NCLS + cc) * NSP + ss) * HWSZ + r * WW + col];
        }
        __syncthreads();

        int sm1 = ((r - 1) % 3 + 3) % 3;
        int sm2 = r % 3;
        int sm3 = (r + 1) % 3;

        float a0 = s_x[cpl][sm1][col0], a1 = s_x[cpl][sm1][col0 + 1];
        float b0 = s_x[cpl][sm2][col0], b1 = s_x[cpl][sm2][col0 + 1];
        float c0 = s_x[cpl][sm3][col0], c1 = s_x[cpl][sm3][col0 + 1];

#pragma unroll 4
        for (int cc2 = 0; cc2 < 48; cc2++) {
            int col = col0 + cc2;
            float a2 = s_x[cpl][sm1][col + 2];
            float b2 = s_x[cpl][sm2][col + 2];
            float c2 = s_x[cpl][sm3][col + 2];
#pragma unroll
            for (int i = 0; i < 4; i++) {
                float sn = s_sp[scg * 4 + i][col];
                acc[i][0] += sn * a0; acc[i][1] += sn * a1; acc[i][2] += sn * a2;
                acc[i][3] += sn * b0; acc[i][4] += sn * b1; acc[i][5] += sn * b2;
                acc[i][6] += sn * c0; acc[i][7] += sn * c1; acc[i][8] += sn * c2;
            }
            a0 = a1; a1 = a2;
            b0 = b1; b1 = b2;
            c0 = c1; c1 = c2;
        }
    }

    int cp = cgrp * 8 + cpl;
#pragma unroll
    for (int i = 0; i < 4; i++) {
        int sc = scg * 4 + i;
        int cc = sc >> 3, ss = sc & 7;
        float* dst = &g_P[(((b * NSP + ss) * NCLS + cc) * CH + cp) * 9];
#pragma unroll
        for (int k = 0; k < 9; k++) atomicAdd(&dst[k], acc[i][k]);
    }
}

// ---------------- kernel 3: tok2[b][c][d] ----------------
// grid (8 s, 2 c, 8 b), block 64 (d)
__global__ void k_tok(const float* __restrict__ Wx, const float* __restrict__ Wcs) {
    __shared__ float s_P[576];
    int s = blockIdx.x, c = blockIdx.y, b = blockIdx.z;
    int d = threadIdx.x;
    for (int m = d; m < 576; m += 64)
        s_P[m] = g_P[(((b * NSP + s) * NCLS + c) * CH) * 9 + m];
    __syncthreads();
    float inv = Wcs[s] / g_S[(b * NCLS + c) * NSP + s];
    const float4* row = (const float4*)(Wx + (s * CH + d) * 576);
    const float4* sp4 = (const float4*)s_P;
    float acc = 0.f;
#pragma unroll 4
    for (int m = 0; m < 144; m++) {
        float4 wv = row[m];
        float4 pv = sp4[m];
        acc += wv.x * pv.x + wv.y * pv.y + wv.z * pv.z + wv.w * pv.w;
    }
    atomicAdd(&g_tok2[(b * NCLS + c) * CH + d], inv * acc);
}

// ---------------- kernel 4: fused info-gen + 3x3 conv + BN partial sums ----------------
// grid (12, 24, 8): tile 16 wide x 8 high per block, block 256.
// smem: s_info[64][10][19] + s_w[8*9*64] + tok2 + coef
__global__ __launch_bounds__(256) void k_conv(const float* __restrict__ cs,
                                              const float* __restrict__ Wcv,
                                              const float* __restrict__ Wa,
                                              const float* __restrict__ Wcomb) {
    extern __shared__ float sm[];
    float* s_info = sm;                  // 64 * 190
    float* s_w    = sm + 64 * 190;       // 4608
    float* s_t2   = s_w + 4608;          // 128
    float* s_q    = s_t2 + 128;          // 8
    float* s_wa   = s_q + 8;             // 8

    int b = blockIdx.z;
    int th0 = blockIdx.y * 8, tw0 = blockIdx.x * 16;
    int tid = threadIdx.x;

    if (tid < 128) s_t2[tid] = g_tok2[b * 128 + tid];
    else if (tid < 136) {
        int s = tid - 128;
        s_q[s] = Wcomb[s] * Wcv[s];
        s_wa[s] = Wa[s];
    }
    __syncthreads();

    // generate info tile (with halo) directly in smem
    if (tid < 180) {
        int r = tid / 18, c2 = tid % 18;
        int gh = th0 + r - 1, gw = tw0 + c2 - 1;
        float g0 = 0.f, g1 = 0.f;
        if (gh >= 0 && gh < HH && gw >= 0 && gw < WW) {
            float cp0 = sigmoidf_(cs[(b * NCLS + 0) * HWSZ + gh * WW + gw]);
            float cp1 = sigmoidf_(cs[(b * NCLS + 1) * HWSZ + gh * WW + gw]);
#pragma unroll
            for (int s = 0; s < 8; s++) {
                g0 += s_q[s] * sigmoidf_(s_wa[s] * cp0);
                g1 += s_q[s] * sigmoidf_(s_wa[s] * cp1);
            }
        }
#pragma unroll
        for (int d = 0; d < 64; d++)
            s_info[d * 190 + r * 19 + c2] = g0 * s_t2[d] + g1 * s_t2[64 + d];
    }

    int og = tid >> 4, pg = tid & 15;
    int row = pg >> 1, colb = (pg & 1) * 8;
    int o0 = og * 4;

    float acc[4][8];
#pragma unroll
    for (int oo = 0; oo < 4; oo++)
#pragma unroll
        for (int j = 0; j < 8; j++) acc[oo][j] = 0.f;

    for (int dc = 0; dc < 8; dc++) {
        __syncthreads();
        {
            float4* sw4 = (float4*)s_w;
            const float4* src = (const float4*)(g_wT + dc * 4608);
            for (int i = tid; i < 1152; i += 256) sw4[i] = src[i];
        }
        __syncthreads();
#pragma unroll
        for (int dl = 0; dl < 8; dl++) {
            const float* ibase = s_info + (dc * 8 + dl) * 190;
            const float* wbase = s_w + dl * 576;
#pragma unroll
            for (int ky = 0; ky < 3; ky++) {
                const float* vrow = ibase + (row + ky) * 19 + colb;
                float v[10];
#pragma unroll
                for (int i = 0; i < 10; i++) v[i] = vrow[i];
#pragma unroll
                for (int kx = 0; kx < 3; kx++) {
                    float4 wv = *(const float4*)(wbase + (ky * 3 + kx) * 64 + o0);
#pragma unroll
                    for (int j = 0; j < 8; j++) {
                        float vv = v[j + kx];
                        acc[0][j] += wv.x * vv;
                        acc[1][j] += wv.y * vv;
                        acc[2][j] += wv.z * vv;
                        acc[3][j] += wv.w * vv;
                    }
                }
            }
        }
    }

    // write y + BN partial sums
#pragma unroll
    for (int oo = 0; oo < 4; oo++) {
        int o = o0 + oo;
        float* dst = g_y + ((b * CH + o) * HH + th0 + row) * WW + tw0 + colb;
        float4 lo = make_float4(acc[oo][0], acc[oo][1], acc[oo][2], acc[oo][3]);
        float4 hi = make_float4(acc[oo][4], acc[oo][5], acc[oo][6], acc[oo][7]);
        *(float4*)(dst) = lo;
        *(float4*)(dst + 4) = hi;

        float ss = 0.f, s2 = 0.f;
#pragma unroll
        for (int j = 0; j < 8; j++) {
            ss += acc[oo][j];
            s2 += acc[oo][j] * acc[oo][j];
        }
#pragma unroll
        for (int off = 8; off; off >>= 1) {
            ss += __shfl_down_sync(0xffffffffu, ss, off, 16);
            s2 += __shfl_down_sync(0xffffffffu, s2, off, 16);
        }
        if ((tid & 15) == 0) {
            atomicAdd(&g_bnsum[o], ss);
            atomicAdd(&g_bnsq[o], s2);
        }
    }
}

// ---------------- kernel 5: BN finalize ----------------
__global__ void k_bnfin(const float* __restrict__ gamma, const float* __restrict__ beta) {
    int o = threadIdx.x;
    const float nInv = 1.0f / (float)(BB * HWSZ);
    float mean = g_bnsum[o] * nInv;
    float var = g_bnsq[o] * nInv - mean * mean;
    float a = gamma[o] * rsqrtf(var + 1e-5f);
    g_bna[o] = a;
    g_bnb[o] = beta[o] - mean * a;
}

// ---------------- kernel 6: out = x + relu(bn(y)) ----------------
__global__ void k_final(const float* __restrict__ x, float* __restrict__ out) {
    int i = blockIdx.x * blockDim.x + threadIdx.x;
    const int n4 = BB * CH * HWSZ / 4;
    if (i >= n4) return;
    int o = (i / (HWSZ / 4)) % CH;
    float a = g_bna[o], bb = g_bnb[o];
    float4 xv = ((const float4*)x)[i];
    float4 yv = ((const float4*)g_y)[i];
    float4 r;
    r.x = xv.x + fmaxf(yv.x * a + bb, 0.f);
    r.y = xv.y + fmaxf(yv.y * a + bb, 0.f);
    r.z = xv.z + fmaxf(yv.z * a + bb, 0.f);
    r.w = xv.w + fmaxf(yv.w * a + bb, 0.f);
    ((float4*)out)[i] = r;
}

// ---------------- launch ----------------
extern "C" void kernel_launch(void* const* d_in, const int* in_sizes, int n_in,
                              void* d_out, int out_size) {
    const float* x      = (const float*)d_in[0];
    const float* cs     = (const float*)d_in[1];
    const float* Wcsp   = (const float*)d_in[2];
    const float* Wx     = (const float*)d_in[3];
    const float* Wcs    = (const float*)d_in[4];
    const float* Wcv    = (const float*)d_in[5];
    const float* Wa     = (const float*)d_in[6];
    const float* Wcomb  = (const float*)d_in[7];
    const float* Wsing  = (const float*)d_in[8];
    const float* gamma  = (const float*)d_in[9];
    const float* beta   = (const float*)d_in[10];
    float* out = (float*)d_out;

    const size_t smem_conv = (64 * 190 + 4608 + 128 + 16) * sizeof(float); // ~67.6 KB
    cudaFuncSetAttribute(k_conv, cudaFuncAttributeMaxDynamicSharedMemorySize, (int)smem_conv);

    k_zero<<<288, 256>>>();
    k_wT<<<144, 256>>>(Wsing);
    k_space<<<dim3(144, 16), 256>>>(cs, Wcsp);
    k_P<<<dim3(12, 8, 8), 128>>>(x);
    k_tok<<<dim3(8, 2, 8), 64>>>(Wx, Wcs);
    k_conv<<<dim3(12, 24, 8), 256, smem_conv>>>(cs, Wcv, Wa, Wcomb);
    k_bnfin<<<1, 64>>>(gamma, beta);
    const int n4 = BB * CH * HWSZ / 4;
    k_final<<<(n4 + 255) / 256, 256>>>(x, out);
}

// round 4
// speedup vs baseline: 1.6584x; 1.6584x over previous
#include <cuda_runtime.h>
#include <math.h>

// Problem constants
constexpr int BB   = 8;     // batch
constexpr int NCLS = 2;     // n_classes
constexpr int NSP  = 8;     // n_space
constexpr int CH   = 64;    // channels
constexpr int HH   = 192;
constexpr int WW   = 192;
constexpr int HWSZ = HH * WW;   // 36864
constexpr int RPS  = 12;    // rows per strip in k_P (16 strips)

typedef unsigned long long u64t;

// ---------------- device scratch ----------------
__device__ float g_space[BB * NCLS * NSP * HWSZ];   // [b][c][s][hw] == [b][sc][hw]
__device__ float g_S[BB * NCLS * NSP];              // spatial sums per (b,c,s)
__device__ float g_P[BB * NSP * NCLS * CH * 9];     // [b][s][c][c'][k]
__device__ float g_tok2[BB * NCLS * CH];            // [b][c][d]
__device__ float g_wT[CH * CH * 9];                 // W_single as [d][k][o]
__device__ float g_U[BB * NCLS * 9 * CH];           // collapsed conv weights [b][c][k][o]
__device__ float g_y[BB * CH * HWSZ];               // conv output pre-BN
__device__ float g_bnsum[CH];
__device__ float g_bnsq[CH];
__device__ float g_bna[CH];
__device__ float g_bnb[CH];

__device__ __forceinline__ float sigmoidf_(float x) {
    return 1.0f / (1.0f + __expf(-x));
}

// ---- packed f32x2 helpers (sm_100+) ----
__device__ __forceinline__ u64t pack2(float lo, float hi) {
    u64t r; asm("mov.b64 %0, {%1, %2};" : "=l"(r) : "f"(lo), "f"(hi)); return r;
}
__device__ __forceinline__ u64t pack1(float v) {
    u64t r; asm("mov.b64 %0, {%1, %1};" : "=l"(r) : "f"(v)); return r;
}
__device__ __forceinline__ u64t ffma2(u64t a, u64t b, u64t c) {
    u64t d; asm("fma.rn.f32x2 %0, %1, %2, %3;" : "=l"(d) : "l"(a), "l"(b), "l"(c)); return d;
}
__device__ __forceinline__ float2 unpack2(u64t v) {
    float2 f; asm("mov.b64 {%0, %1}, %2;" : "=f"(f.x), "=f"(f.y) : "l"(v)); return f;
}

// ---------------- kernel 0: zero accumulators ----------------
__global__ void k_zero() {
    int i = blockIdx.x * blockDim.x + threadIdx.x;
    if (i < BB * NSP * NCLS * CH * 9) g_P[i] = 0.f;
    if (i < BB * NCLS * NSP) g_S[i] = 0.f;
    if (i < BB * NCLS * CH) g_tok2[i] = 0.f;
    if (i < CH) { g_bnsum[i] = 0.f; g_bnsq[i] = 0.f; }
}

// ---------------- kernel 0b: transpose W_single (OIHW -> [d][k][o]) ----------------
__global__ void k_wT(const float* __restrict__ Ws) {
    int i = blockIdx.x * blockDim.x + threadIdx.x;
    if (i < CH * CH * 9) {
        int o = i / 576;
        int rem = i % 576;
        int d = rem / 9;
        int k = rem % 9;
        g_wT[d * 576 + k * 64 + o] = Ws[i];
    }
}

// ---------------- kernel 1: class_prob -> space channels + spatial sums ----------------
__global__ void k_space(const float* __restrict__ cs, const float* __restrict__ Wcsp) {
    int bc = blockIdx.y;
    int p = blockIdx.x * 256 + threadIdx.x;       // 144*256 == HWSZ
    int h = p / WW, w = p % WW;
    const float* base = cs + bc * HWSZ;

    float n[9];
#pragma unroll
    for (int dy = 0; dy < 3; dy++) {
#pragma unroll
        for (int dx = 0; dx < 3; dx++) {
            int gh = h + dy - 1, gw = w + dx - 1;
            float v = 0.f;
            if (gh >= 0 && gh < HH && gw >= 0 && gw < WW)
                v = sigmoidf_(base[gh * WW + gw]);
            n[dy * 3 + dx] = v;
        }
    }

    float sums[NSP];
    float ch0 = n[4];
    g_space[(bc * NSP + 0) * HWSZ + p] = ch0;
    sums[0] = ch0;
#pragma unroll
    for (int j = 0; j < 7; j++) {
        float z = 0.f;
#pragma unroll
        for (int k = 0; k < 9; k++) z += Wcsp[j * 9 + k] * n[k];
        float v = sigmoidf_(z);
        g_space[(bc * NSP + j + 1) * HWSZ + p] = v;
        sums[j + 1] = v;
    }

#pragma unroll
    for (int s = 0; s < NSP; s++) {
        float v = sums[s];
#pragma unroll
        for (int off = 16; off; off >>= 1)
            v += __shfl_down_sync(0xffffffffu, v, off);
        if ((threadIdx.x & 31) == 0) atomicAdd(&g_S[bc * NSP + s], v);
    }
}

// ---------------- kernel 2: P correlation (f32x2, sc in lanes) ----------------
// grid (16 strips, 8 c'-groups, 8 b), block 128.
// s_x: [cp][slot][col+1], per-cp stride 612 (== 4 mod 32 banks), slot stride 204.
__device__ __forceinline__ void load_x_row2(float* s_x, const float* __restrict__ xb,
                                            int grow, int tid) {
    int slot = ((grow % 3) + 3) % 3;
    bool rok = (grow >= 0 && grow < HH);
    for (int i = tid; i < 8 * 194; i += 128) {
        int cp = i / 194, cc = i - cp * 194;
        int gcol = cc - 1;
        float v = 0.f;
        if (rok && gcol >= 0 && gcol < WW) v = xb[cp * HWSZ + grow * WW + gcol];
        s_x[cp * 612 + slot * 204 + cc] = v;
    }
}

__global__ __launch_bounds__(128) void k_P(const float* __restrict__ x) {
    __shared__ __align__(16) float s_x[8 * 612];
    __shared__ __align__(16) float s_spT[192 * 18];   // [col][sc], stride 18

    int b = blockIdx.z, cgrp = blockIdx.y, strip = blockIdx.x;
    int r0 = strip * RPS;
    int tid = threadIdx.x;
    int scq = tid >> 5;          // 0..3, each warp handles 4 sc (2 f32x2 pairs)
    int lane = tid & 31;
    int cpl = lane >> 2;         // 0..7 local c'
    int chunk = lane & 3;        // 0..3 -> 48-col chunk
    int col0 = chunk * 48;
    int scb = scq * 4;

    u64t acc[2][9];
#pragma unroll
    for (int i = 0; i < 2; i++)
#pragma unroll
        for (int k = 0; k < 9; k++) acc[i][k] = 0ull;

    const float* xb = x + (size_t)(b * CH + cgrp * 8) * HWSZ;
    const float* spb = g_space + (size_t)b * 16 * HWSZ;

    load_x_row2(s_x, xb, r0 - 1, tid);
    load_x_row2(s_x, xb, r0, tid);

    for (int r = r0; r < r0 + RPS; r++) {
        __syncthreads();
        load_x_row2(s_x, xb, r + 1, tid);
        {
            const float* sp_row = spb + r * WW;
#pragma unroll
            for (int j = 0; j < 24; j++) {
                int i = tid + j * 128;
                int sc = i / 192;
                int col = i - sc * 192;
                s_spT[col * 18 + sc] = sp_row[sc * HWSZ + col];
            }
        }
        __syncthreads();

        int sm1 = (r + 2) % 3;   // slot of row r-1
        int sm0 = r % 3;         // slot of row r
        int sp1 = (r + 1) % 3;   // slot of row r+1
        const float* xr0 = s_x + cpl * 612 + sm1 * 204;
        const float* xr1 = s_x + cpl * 612 + sm0 * 204;
        const float* xr2 = s_x + cpl * 612 + sp1 * 204;

        // sliding broadcast-packed x values: m=x[col-1], c=x[col]
        u64t m0 = pack1(xr0[col0]);
        u64t m1 = pack1(xr1[col0]);
        u64t m2 = pack1(xr2[col0]);
        u64t c0 = pack1(xr0[col0 + 1]);
        u64t c1 = pack1(xr1[col0 + 1]);
        u64t c2 = pack1(xr2[col0 + 1]);
        const float* snp = s_spT + col0 * 18 + scb;

#pragma unroll 4
        for (int cc = 0; cc < 48; cc++) {
            int col = col0 + cc;
            u64t p0 = pack1(xr0[col + 2]);   // x[col+1]
            u64t p1 = pack1(xr1[col + 2]);
            u64t p2 = pack1(xr2[col + 2]);
            u64t snA = *(const u64t*)(snp);       // sc scb, scb+1
            u64t snB = *(const u64t*)(snp + 2);   // sc scb+2, scb+3

            acc[0][0] = ffma2(snA, m0, acc[0][0]);
            acc[0][1] = ffma2(snA, c0, acc[0][1]);
            acc[0][2] = ffma2(snA, p0, acc[0][2]);
            acc[0][3] = ffma2(snA, m1, acc[0][3]);
            acc[0][4] = ffma2(snA, c1, acc[0][4]);
            acc[0][5] = ffma2(snA, p1, acc[0][5]);
            acc[0][6] = ffma2(snA, m2, acc[0][6]);
            acc[0][7] = ffma2(snA, c2, acc[0][7]);
            acc[0][8] = ffma2(snA, p2, acc[0][8]);

            acc[1][0] = ffma2(snB, m0, acc[1][0]);
            acc[1][1] = ffma2(snB, c0, acc[1][1]);
            acc[1][2] = ffma2(snB, p0, acc[1][2]);
            acc[1][3] = ffma2(snB, m1, acc[1][3]);
            acc[1][4] = ffma2(snB, c1, acc[1][4]);
            acc[1][5] = ffma2(snB, p1, acc[1][5]);
            acc[1][6] = ffma2(snB, m2, acc[1][6]);
            acc[1][7] = ffma2(snB, c2, acc[1][7]);
            acc[1][8] = ffma2(snB, p2, acc[1][8]);

            m0 = c0; c0 = p0;
            m1 = c1; c1 = p1;
            m2 = c2; c2 = p2;
            snp += 18;
        }
    }

    int cp = cgrp * 8 + cpl;
#pragma unroll
    for (int scp = 0; scp < 2; scp++) {
        int sc0 = scb + scp * 2;
        int sc1 = sc0 + 1;
        int sA = sc0 & 7, cA = sc0 >> 3;
        int sB = sc1 & 7, cB = sc1 >> 3;
        float* dA = &g_P[(((b * 8 + sA) * 2 + cA) * 64 + cp) * 9];
        float* dB = &g_P[(((b * 8 + sB) * 2 + cB) * 64 + cp) * 9];
#pragma unroll
        for (int k = 0; k < 9; k++) {
            float2 v = unpack2(acc[scp][k]);
            atomicAdd(&dA[k], v.x);
            atomicAdd(&dB[k], v.y);
        }
    }
}

// ---------------- kernel 3: tok2[b][c][d] ----------------
__global__ void k_tok(const float* __restrict__ Wx, const float* __restrict__ Wcs) {
    __shared__ float s_P[576];
    int s = blockIdx.x, c = blockIdx.y, b = blockIdx.z;
    int d = threadIdx.x;
    for (int m = d; m < 576; m += 64)
        s_P[m] = g_P[(((b * NSP + s) * NCLS + c) * CH) * 9 + m];
    __syncthreads();
    float inv = Wcs[s] / g_S[(b * NCLS + c) * NSP + s];
    const float4* row = (const float4*)(Wx + (s * CH + d) * 576);
    const float4* sp4 = (const float4*)s_P;
    float acc = 0.f;
#pragma unroll 4
    for (int m = 0; m < 144; m++) {
        float4 wv = row[m];
        float4 pv = sp4[m];
        acc += wv.x * pv.x + wv.y * pv.y + wv.z * pv.z + wv.w * pv.w;
    }
    atomicAdd(&g_tok2[(b * NCLS + c) * CH + d], inv * acc);
}

// ---------------- kernel 3b: collapsed conv weights U[b][c][k][o] ----------------
__global__ void k_U() {
    __shared__ float s_t[128];
    int b = blockIdx.x;
    if (threadIdx.x < 128) s_t[threadIdx.x] = g_tok2[b * 128 + threadIdx.x];
    __syncthreads();
    for (int idx = threadIdx.x; idx < 1152; idx += blockDim.x) {
        int o = idx & 63;
        int ck = idx >> 6;
        int c = ck / 9, k = ck % 9;
        float acc = 0.f;
#pragma unroll 8
        for (int d = 0; d < 64; d++)
            acc += g_wT[d * 576 + k * 64 + o] * s_t[c * 64 + d];
        g_U[((b * 2 + c) * 9 + k) * 64 + o] = acc;
    }
}

// ---------------- kernel 4: fused g-gen + 2-channel 3x3 conv + BN partial sums ----------------
// grid (12, 24, 8): tile 16 wide x 8 high, block 256.
__global__ __launch_bounds__(256) void k_conv2(const float* __restrict__ cs,
                                               const float* __restrict__ Wcv,
                                               const float* __restrict__ Wa,
                                               const float* __restrict__ Wcomb) {
    __shared__ float s_g[2][10][19];
    __shared__ float s_U[2][9][64];
    __shared__ float s_q[8], s_wa[8];

    int b = blockIdx.z;
    int th0 = blockIdx.y * 8, tw0 = blockIdx.x * 16;
    int tid = threadIdx.x;

    if (tid < 8) {
        s_q[tid] = Wcomb[tid] * Wcv[tid];
        s_wa[tid] = Wa[tid];
    }
    // load U (1152 floats = 288 float4)
    {
        float4* dst = (float4*)s_U;
        const float4* src = (const float4*)(g_U + b * 1152);
        for (int i = tid; i < 288; i += 256) dst[i] = src[i];
    }
    __syncthreads();

    // generate g tile (with halo)
    if (tid < 180) {
        int r = tid / 18, c2 = tid % 18;
        int gh = th0 + r - 1, gw = tw0 + c2 - 1;
        float g0 = 0.f, g1 = 0.f;
        if (gh >= 0 && gh < HH && gw >= 0 && gw < WW) {
            float cp0 = sigmoidf_(cs[(b * NCLS + 0) * HWSZ + gh * WW + gw]);
            float cp1 = sigmoidf_(cs[(b * NCLS + 1) * HWSZ + gh * WW + gw]);
#pragma unroll
            for (int s = 0; s < 8; s++) {
                g0 += s_q[s] * sigmoidf_(s_wa[s] * cp0);
                g1 += s_q[s] * sigmoidf_(s_wa[s] * cp1);
            }
        }
        s_g[0][r][c2] = g0;
        s_g[1][r][c2] = g1;
    }
    __syncthreads();

    int og = tid >> 4, pg = tid & 15;
    int row = pg >> 1, colb = (pg & 1) * 8;
    int o0 = og * 4;

    float acc[4][8];
#pragma unroll
    for (int oo = 0; oo < 4; oo++)
#pragma unroll
        for (int j = 0; j < 8; j++) acc[oo][j] = 0.f;

#pragma unroll
    for (int c = 0; c < 2; c++) {
#pragma unroll
        for (int ky = 0; ky < 3; ky++) {
            const float* vrow = &s_g[c][row + ky][colb];
            float v[10];
#pragma unroll
            for (int i = 0; i < 10; i++) v[i] = vrow[i];
#pragma unroll
            for (int kx = 0; kx < 3; kx++) {
                float4 wv = *(const float4*)&s_U[c][ky * 3 + kx][o0];
#pragma unroll
                for (int j = 0; j < 8; j++) {
                    float vv = v[j + kx];
                    acc[0][j] += wv.x * vv;
                    acc[1][j] += wv.y * vv;
                    acc[2][j] += wv.z * vv;
                    acc[3][j] += wv.w * vv;
                }
            }
        }
    }

    // write y + BN partial sums
#pragma unroll
    for (int oo = 0; oo < 4; oo++) {
        int o = o0 + oo;
        float* dst = g_y + (((size_t)b * CH + o) * HH + th0 + row) * WW + tw0 + colb;
        *(float4*)(dst) = make_float4(acc[oo][0], acc[oo][1], acc[oo][2], acc[oo][3]);
        *(float4*)(dst + 4) = make_float4(acc[oo][4], acc[oo][5], acc[oo][6], acc[oo][7]);

        float ss = 0.f, s2 = 0.f;
#pragma unroll
        for (int j = 0; j < 8; j++) {
            ss += acc[oo][j];
            s2 += acc[oo][j] * acc[oo][j];
        }
#pragma unroll
        for (int off = 8; off; off >>= 1) {
            ss += __shfl_down_sync(0xffffffffu, ss, off, 16);
            s2 += __shfl_down_sync(0xffffffffu, s2, off, 16);
        }
        if ((tid & 15) == 0) {
            atomicAdd(&g_bnsum[o], ss);
            atomicAdd(&g_bnsq[o], s2);
        }
    }
}

// ---------------- kernel 5: BN finalize ----------------
__global__ void k_bnfin(const float* __restrict__ gamma, const float* __restrict__ beta) {
    int o = threadIdx.x;
    const float nInv = 1.0f / (float)(BB * HWSZ);
    float mean = g_bnsum[o] * nInv;
    float var = g_bnsq[o] * nInv - mean * mean;
    float a = gamma[o] * rsqrtf(var + 1e-5f);
    g_bna[o] = a;
    g_bnb[o] = beta[o] - mean * a;
}

// ---------------- kernel 6: out = x + relu(bn(y)) ----------------
__global__ void k_final(const float* __restrict__ x, float* __restrict__ out) {
    int i = blockIdx.x * blockDim.x + threadIdx.x;
    const int n4 = BB * CH * HWSZ / 4;
    if (i >= n4) return;
    int o = (i / (HWSZ / 4)) % CH;
    float a = g_bna[o], bb = g_bnb[o];
    float4 xv = ((const float4*)x)[i];
    float4 yv = ((const float4*)g_y)[i];
    float4 r;
    r.x = xv.x + fmaxf(yv.x * a + bb, 0.f);
    r.y = xv.y + fmaxf(yv.y * a + bb, 0.f);
    r.z = xv.z + fmaxf(yv.z * a + bb, 0.f);
    r.w = xv.w + fmaxf(yv.w * a + bb, 0.f);
    ((float4*)out)[i] = r;
}

// ---------------- launch ----------------
extern "C" void kernel_launch(void* const* d_in, const int* in_sizes, int n_in,
                              void* d_out, int out_size) {
    const float* x      = (const float*)d_in[0];
    const float* cs     = (const float*)d_in[1];
    const float* Wcsp   = (const float*)d_in[2];
    const float* Wx     = (const float*)d_in[3];
    const float* Wcs    = (const float*)d_in[4];
    const float* Wcv    = (const float*)d_in[5];
    const float* Wa     = (const float*)d_in[6];
    const float* Wcomb  = (const float*)d_in[7];
    const float* Wsing  = (const float*)d_in[8];
    const float* gamma  = (const float*)d_in[9];
    const float* beta   = (const float*)d_in[10];
    float* out = (float*)d_out;

    k_zero<<<288, 256>>>();
    k_wT<<<144, 256>>>(Wsing);
    k_space<<<dim3(144, 16), 256>>>(cs, Wcsp);
    k_P<<<dim3(16, 8, 8), 128>>>(x);
    k_tok<<<dim3(8, 2, 8), 64>>>(Wx, Wcs);
    k_U<<<8, 256>>>();
    k_conv2<<<dim3(12, 24, 8), 256>>>(cs, Wcv, Wa, Wcomb);
    k_bnfin<<<1, 64>>>(gamma, beta);
    const int n4 = BB * CH * HWSZ / 4;
    k_final<<<(n4 + 255) / 256, 256>>>(x, out);
}

// round 7
// speedup vs baseline: 1.9754x; 1.1912x over previous
#include <cuda_runtime.h>
#include <math.h>

// Problem constants
constexpr int BB   = 8;
constexpr int NCLS = 2;
constexpr int NSP  = 8;
constexpr int CH   = 64;
constexpr int HH   = 192;
constexpr int WW   = 192;
constexpr int HWSZ = HH * WW;   // 36864
constexpr int RPS  = 12;        // rows per strip in k_P (16 strips)

// k_P smem layout constants
constexpr int XCHUNK = 56;                 // 50 used + 6 pad
constexpr int XSLOT  = 4 * XCHUNK;         // 224 floats per row-slot
constexpr int XCP    = 3 * XSLOT + 1;      // 673 (odd -> cpl banks distinct mod 8)
constexpr int SPCOLSTRIDE = 18;            // [col][sc] stride
// spidx(col) = col*18 + 2*(col/48); max 191*18+6+15 = 3459
constexpr int SPSZ = 3464;

typedef unsigned long long u64t;

// ---------------- device scratch ----------------
__device__ float g_space[BB * NCLS * NSP * HWSZ];   // [b][sc][hw]
__device__ float g_S[BB * NCLS * NSP];
__device__ float g_P[BB * NSP * NCLS * CH * 9];     // [b][s][c][c'][k]
__device__ float g_tok2[BB * NCLS * CH];            // [b][c][d]
__device__ float g_wT[CH * CH * 9];                 // [d][k][o]
__device__ float g_U[BB * NCLS * 9 * CH];           // [b][c][k][o]
__device__ float g_g[BB * NCLS * HWSZ];             // [b][c][hw]  rank-2 input maps
__device__ float g_bnsum[CH];
__device__ float g_bnsq[CH];
__device__ float g_bna[CH];
__device__ float g_bnb[CH];

__device__ __forceinline__ float sigmoidf_(float x) {
    return 1.0f / (1.0f + __expf(-x));
}

// ---- packed f32x2 helpers ----
__device__ __forceinline__ u64t pack1(float v) {
    u64t r; asm("mov.b64 %0, {%1, %1};" : "=l"(r) : "f"(v)); return r;
}
__device__ __forceinline__ u64t ffma2(u64t a, u64t b, u64t c) {
    u64t d; asm("fma.rn.f32x2 %0, %1, %2, %3;" : "=l"(d) : "l"(a), "l"(b), "l"(c)); return d;
}
__device__ __forceinline__ float2 unpack2(u64t v) {
    float2 f; asm("mov.b64 {%0, %1}, %2;" : "=f"(f.x), "=f"(f.y) : "l"(v)); return f;
}

// ---------------- kernel: zero accumulators + transpose W_single ----------------
__global__ void k_init(const float* __restrict__ Ws) {
    int i = blockIdx.x * blockDim.x + threadIdx.x;
    if (i < BB * NSP * NCLS * CH * 9) g_P[i] = 0.f;
    if (i < BB * NCLS * NSP) g_S[i] = 0.f;
    if (i < BB * NCLS * CH) g_tok2[i] = 0.f;
    if (i < CH) { g_bnsum[i] = 0.f; g_bnsq[i] = 0.f; }
    if (i < CH * CH * 9) {
        int o = i / 576;
        int rem = i % 576;
        int d = rem / 9;
        int k = rem % 9;
        g_wT[d * 576 + k * 64 + o] = Ws[i];
    }
}

// ---------------- kernel 1: space channels + spatial sums ----------------
__global__ void k_space(const float* __restrict__ cs, const float* __restrict__ Wcsp) {
    int bc = blockIdx.y;
    int p = blockIdx.x * 256 + threadIdx.x;       // 144*256 == HWSZ
    int h = p / WW, w = p % WW;
    const float* base = cs + bc * HWSZ;

    float n[9];
#pragma unroll
    for (int dy = 0; dy < 3; dy++) {
#pragma unroll
        for (int dx = 0; dx < 3; dx++) {
            int gh = h + dy - 1, gw = w + dx - 1;
            float v = 0.f;
            if (gh >= 0 && gh < HH && gw >= 0 && gw < WW)
                v = sigmoidf_(base[gh * WW + gw]);
            n[dy * 3 + dx] = v;
        }
    }

    float sums[NSP];
    float ch0 = n[4];
    g_space[(bc * NSP + 0) * HWSZ + p] = ch0;
    sums[0] = ch0;
#pragma unroll
    for (int j = 0; j < 7; j++) {
        float z = 0.f;
#pragma unroll
        for (int k = 0; k < 9; k++) z += Wcsp[j * 9 + k] * n[k];
        float v = sigmoidf_(z);
        g_space[(bc * NSP + j + 1) * HWSZ + p] = v;
        sums[j + 1] = v;
    }

#pragma unroll
    for (int s = 0; s < NSP; s++) {
        float v = sums[s];
#pragma unroll
        for (int off = 16; off; off >>= 1)
            v += __shfl_down_sync(0xffffffffu, v, off);
        if ((threadIdx.x & 31) == 0) atomicAdd(&g_S[bc * NSP + s], v);
    }
}

// ---------------- kernel 1b: g maps (rank-2 pixel weights) ----------------
__global__ void k_g(const float* __restrict__ cs,
                    const float* __restrict__ Wcv,
                    const float* __restrict__ Wa,
                    const float* __restrict__ Wcomb) {
    __shared__ float s_q[8], s_wa[8];
    if (threadIdx.x < 8) {
        s_q[threadIdx.x] = Wcomb[threadIdx.x] * Wcv[threadIdx.x];
        s_wa[threadIdx.x] = Wa[threadIdx.x];
    }
    __syncthreads();
    int i = blockIdx.x * blockDim.x + threadIdx.x;    // over b*HWSZ
    if (i >= BB * HWSZ) return;
    int b = i / HWSZ, p = i % HWSZ;
    float cp0 = sigmoidf_(cs[(b * NCLS + 0) * HWSZ + p]);
    float cp1 = sigmoidf_(cs[(b * NCLS + 1) * HWSZ + p]);
    float g0 = 0.f, g1 = 0.f;
#pragma unroll
    for (int s = 0; s < 8; s++) {
        g0 += s_q[s] * sigmoidf_(s_wa[s] * cp0);
        g1 += s_q[s] * sigmoidf_(s_wa[s] * cp1);
    }
    g_g[(b * NCLS + 0) * HWSZ + p] = g0;
    g_g[(b * NCLS + 1) * HWSZ + p] = g1;
}

// ---------------- kernel 2: P correlation (conflict-free smem) ----------------
// s_x: [cp][slot][chunk j][t], t=0..49 holds cols 48j-1 .. 48j+48 (halo duplicated)
__device__ __forceinline__ void load_x_row3(float* s_x, const float* __restrict__ xb,
                                            int grow, int tid) {
    int slot = ((grow % 3) + 3) % 3;
    bool rok = (grow >= 0 && grow < HH);
    for (int i = tid; i < 8 * 200; i += 128) {
        int cp = i / 200, e = i - cp * 200;
        int j = e / 50, t = e - j * 50;
        int col = 48 * j - 1 + t;
        float v = 0.f;
        if (rok && col >= 0 && col < WW) v = xb[cp * HWSZ + grow * WW + col];
        s_x[cp * XCP + slot * XSLOT + j * XCHUNK + t] = v;
    }
}

__global__ __launch_bounds__(128) void k_P(const float* __restrict__ x) {
    __shared__ __align__(16) float s_x[8 * XCP];
    __shared__ __align__(16) float s_spT[SPSZ];

    int b = blockIdx.z, cgrp = blockIdx.y, strip = blockIdx.x;
    int r0 = strip * RPS;
    int tid = threadIdx.x;
    int scq = tid >> 5;          // warp id -> 4 sc (2 f32x2 pairs)
    int lane = tid & 31;
    int cpl = lane >> 2;         // 0..7 local c'
    int j = lane & 3;            // chunk 0..3 (48 cols each)
    int scb = scq * 4;

    u64t acc[2][9];
#pragma unroll
    for (int i = 0; i < 2; i++)
#pragma unroll
        for (int k = 0; k < 9; k++) acc[i][k] = 0ull;

    const float* xb = x + (size_t)(b * CH + cgrp * 8) * HWSZ;
    const float* spb = g_space + (size_t)b * 16 * HWSZ;

    load_x_row3(s_x, xb, r0 - 1, tid);
    load_x_row3(s_x, xb, r0, tid);

    const int xoff = cpl * XCP + j * XCHUNK;
    const int spoff = 866 * j + scb;   // (48j)*18 + 2j + scb

    for (int r = r0; r < r0 + RPS; r++) {
        __syncthreads();
        load_x_row3(s_x, xb, r + 1, tid);
        {
            const float* sp_row = spb + r * WW;
#pragma unroll
            for (int jj = 0; jj < 24; jj++) {
                int i = tid + jj * 128;
                int sc = i / 192;
                int col = i - sc * 192;
                s_spT[col * SPCOLSTRIDE + 2 * (col / 48) + sc] = sp_row[sc * HWSZ + col];
            }
        }
        __syncthreads();

        int sm1 = (r + 2) % 3;
        int sm0 = r % 3;
        int sp1 = (r + 1) % 3;
        const float* xr0 = s_x + xoff + sm1 * XSLOT;
        const float* xr1 = s_x + xoff + sm0 * XSLOT;
        const float* xr2 = s_x + xoff + sp1 * XSLOT;

        u64t m0 = pack1(xr0[0]);
        u64t m1 = pack1(xr1[0]);
        u64t m2 = pack1(xr2[0]);
        u64t c0 = pack1(xr0[1]);
        u64t c1 = pack1(xr1[1]);
        u64t c2 = pack1(xr2[1]);
        const float* snp = s_spT + spoff;

#pragma unroll 4
        for (int cc = 0; cc < 48; cc++) {
            u64t p0 = pack1(xr0[cc + 2]);
            u64t p1 = pack1(xr1[cc + 2]);
            u64t p2 = pack1(xr2[cc + 2]);
            u64t snA = *(const u64t*)(snp);
            u64t snB = *(const u64t*)(snp + 2);

            acc[0][0] = ffma2(snA, m0, acc[0][0]);
            acc[0][1] = ffma2(snA, c0, acc[0][1]);
            acc[0][2] = ffma2(snA, p0, acc[0][2]);
            acc[0][3] = ffma2(snA, m1, acc[0][3]);
            acc[0][4] = ffma2(snA, c1, acc[0][4]);
            acc[0][5] = ffma2(snA, p1, acc[0][5]);
            acc[0][6] = ffma2(snA, m2, acc[0][6]);
            acc[0][7] = ffma2(snA, c2, acc[0][7]);
            acc[0][8] = ffma2(snA, p2, acc[0][8]);

            acc[1][0] = ffma2(snB, m0, acc[1][0]);
            acc[1][1] = ffma2(snB, c0, acc[1][1]);
            acc[1][2] = ffma2(snB, p0, acc[1][2]);
            acc[1][3] = ffma2(snB, m1, acc[1][3]);
            acc[1][4] = ffma2(snB, c1, acc[1][4]);
            acc[1][5] = ffma2(snB, p1, acc[1][5]);
            acc[1][6] = ffma2(snB, m2, acc[1][6]);
            acc[1][7] = ffma2(snB, c2, acc[1][7]);
            acc[1][8] = ffma2(snB, p2, acc[1][8]);

            m0 = c0; c0 = p0;
            m1 = c1; c1 = p1;
            m2 = c2; c2 = p2;
            snp += SPCOLSTRIDE;
        }
    }

    int cp = cgrp * 8 + cpl;
#pragma unroll
    for (int scp = 0; scp < 2; scp++) {
        int sc0 = scb + scp * 2;
        int sc1 = sc0 + 1;
        int sA = sc0 & 7, cA = sc0 >> 3;
        int sB = sc1 & 7, cB = sc1 >> 3;
        float* dA = &g_P[(((b * 8 + sA) * 2 + cA) * 64 + cp) * 9];
        float* dB = &g_P[(((b * 8 + sB) * 2 + cB) * 64 + cp) * 9];
#pragma unroll
        for (int k = 0; k < 9; k++) {
            float2 v = unpack2(acc[scp][k]);
            atomicAdd(&dA[k], v.x);
            atomicAdd(&dB[k], v.y);
        }
    }
}

// ---------------- kernel 3: tok2[b][c][d] ----------------
__global__ void k_tok(const float* __restrict__ Wx, const float* __restrict__ Wcs) {
    __shared__ float s_P[576];
    int s = blockIdx.x, c = blockIdx.y, b = blockIdx.z;
    int d = threadIdx.x;
    for (int m = d; m < 576; m += 64)
        s_P[m] = g_P[(((b * NSP + s) * NCLS + c) * CH) * 9 + m];
    __syncthreads();
    float inv = Wcs[s] / g_S[(b * NCLS + c) * NSP + s];
    const float4* row = (const float4*)(Wx + (s * CH + d) * 576);
    const float4* sp4 = (const float4*)s_P;
    float acc = 0.f;
#pragma unroll 4
    for (int m = 0; m < 144; m++) {
        float4 wv = row[m];
        float4 pv = sp4[m];
        acc += wv.x * pv.x + wv.y * pv.y + wv.z * pv.z + wv.w * pv.w;
    }
    atomicAdd(&g_tok2[(b * NCLS + c) * CH + d], inv * acc);
}

// ---------------- kernel 3b: collapsed conv weights U[b][c][k][o] ----------------
__global__ void k_U() {
    __shared__ float s_t[128];
    int b = blockIdx.x;
    if (threadIdx.x < 128) s_t[threadIdx.x] = g_tok2[b * 128 + threadIdx.x];
    __syncthreads();
    for (int idx = threadIdx.x; idx < 1152; idx += blockDim.x) {
        int o = idx & 63;
        int ck = idx >> 6;
        int c = ck / 9, k = ck % 9;
        float acc = 0.f;
#pragma unroll 8
        for (int d = 0; d < 64; d++)
            acc += g_wT[d * 576 + k * 64 + o] * s_t[c * 64 + d];
        g_U[((b * 2 + c) * 9 + k) * 64 + o] = acc;
    }
}

// ---------------- shared tile-conv helper ----------------
__device__ __forceinline__ void conv_tile(const float s_g[2][10][19],
                                          const float s_U[2][9][64],
                                          int tid, float acc[4][8]) {
    int og = tid >> 4, pg = tid & 15;
    int row = pg >> 1, colb = (pg & 1) * 8;
    int o0 = og * 4;
#pragma unroll
    for (int oo = 0; oo < 4; oo++)
#pragma unroll
        for (int jj = 0; jj < 8; jj++) acc[oo][jj] = 0.f;
#pragma unroll
    for (int c = 0; c < 2; c++) {
#pragma unroll
        for (int ky = 0; ky < 3; ky++) {
            const float* vrow = &s_g[c][row + ky][colb];
            float v[10];
#pragma unroll
            for (int i = 0; i < 10; i++) v[i] = vrow[i];
#pragma unroll
            for (int kx = 0; kx < 3; kx++) {
                float4 wv = *(const float4*)&s_U[c][ky * 3 + kx][o0];
#pragma unroll
                for (int jj = 0; jj < 8; jj++) {
                    float vv = v[jj + kx];
                    acc[0][jj] += wv.x * vv;
                    acc[1][jj] += wv.y * vv;
                    acc[2][jj] += wv.z * vv;
                    acc[3][jj] += wv.w * vv;
                }
            }
        }
    }
}

__device__ __forceinline__ void load_gU_tiles(float s_g[2][10][19], float s_U[2][9][64],
                                              int b, int th0, int tw0, int tid) {
    {
        float4* dst = (float4*)s_U;
        const float4* src = (const float4*)(g_U + b * 1152);
        for (int i = tid; i < 288; i += 256) dst[i] = src[i];
    }
    if (tid < 180) {
        int r = tid / 18, c2 = tid % 18;
        int gh = th0 + r - 1, gw = tw0 + c2 - 1;
        float v0 = 0.f, v1 = 0.f;
        if (gh >= 0 && gh < HH && gw >= 0 && gw < WW) {
            v0 = g_g[(b * NCLS + 0) * HWSZ + gh * WW + gw];
            v1 = g_g[(b * NCLS + 1) * HWSZ + gh * WW + gw];
        }
        s_g[0][r][c2] = v0;
        s_g[1][r][c2] = v1;
    }
}

// ---------------- kernel 4: BN statistics pass (no y write) ----------------
__global__ __launch_bounds__(256) void k_bnstats() {
    __shared__ float s_g[2][10][19];
    __shared__ float s_U[2][9][64];
    int b = blockIdx.z;
    int th0 = blockIdx.y * 8, tw0 = blockIdx.x * 16;
    int tid = threadIdx.x;
    load_gU_tiles(s_g, s_U, b, th0, tw0, tid);
    __syncthreads();

    float acc[4][8];
    conv_tile(s_g, s_U, tid, acc);

    int og = tid >> 4;
    int o0 = og * 4;
#pragma unroll
    for (int oo = 0; oo < 4; oo++) {
        int o = o0 + oo;
        float ss = 0.f, s2 = 0.f;
#pragma unroll
        for (int jj = 0; jj < 8; jj++) {
            ss += acc[oo][jj];
            s2 += acc[oo][jj] * acc[oo][jj];
        }
#pragma unroll
        for (int off = 8; off; off >>= 1) {
            ss += __shfl_down_sync(0xffffffffu, ss, off, 16);
            s2 += __shfl_down_sync(0xffffffffu, s2, off, 16);
        }
        if ((tid & 15) == 0) {
            atomicAdd(&g_bnsum[o], ss);
            atomicAdd(&g_bnsq[o], s2);
        }
    }
}

// ---------------- kernel 5: BN finalize ----------------
__global__ void k_bnfin(const float* __restrict__ gamma, const float* __restrict__ beta) {
    int o = threadIdx.x;
    const float nInv = 1.0f / (float)(BB * HWSZ);
    float mean = g_bnsum[o] * nInv;
    float var = g_bnsq[o] * nInv - mean * mean;
    float a = gamma[o] * rsqrtf(var + 1e-5f);
    g_bna[o] = a;
    g_bnb[o] = beta[o] - mean * a;
}

// ---------------- kernel 6: recompute conv, fuse BN+ReLU+residual ----------------
__global__ __launch_bounds__(256) void k_final(const float* __restrict__ x,
                                               float* __restrict__ out) {
    __shared__ float s_g[2][10][19];
    __shared__ float s_U[2][9][64];
    __shared__ float s_a[64], s_b[64];
    int b = blockIdx.z;
    int th0 = blockIdx.y * 8, tw0 = blockIdx.x * 16;
    int tid = threadIdx.x;
    load_gU_tiles(s_g, s_U, b, th0, tw0, tid);
    if (tid >= 192 && tid < 256) {
        int o = tid - 192;
        s_a[o] = g_bna[o];
        s_b[o] = g_bnb[o];
    }
    __syncthreads();

    float acc[4][8];
    conv_tile(s_g, s_U, tid, acc);

    int og = tid >> 4, pg = tid & 15;
    int row = pg >> 1, colb = (pg & 1) * 8;
    int o0 = og * 4;
#pragma unroll
    for (int oo = 0; oo < 4; oo++) {
        int o = o0 + oo;
        float a = s_a[o], bb = s_b[o];
        size_t off = (((size_t)b * CH + o) * HH + th0 + row) * WW + tw0 + colb;
        const float4 xlo = *(const float4*)(x + off);
        const float4 xhi = *(const float4*)(x + off + 4);
        float4 rlo, rhi;
        rlo.x = xlo.x + fmaxf(acc[oo][0] * a + bb, 0.f);
        rlo.y = xlo.y + fmaxf(acc[oo][1] * a + bb, 0.f);
        rlo.z = xlo.z + fmaxf(acc[oo][2] * a + bb, 0.f);
        rlo.w = xlo.w + fmaxf(acc[oo][3] * a + bb, 0.f);
        rhi.x = xhi.x + fmaxf(acc[oo][4] * a + bb, 0.f);
        rhi.y = xhi.y + fmaxf(acc[oo][5] * a + bb, 0.f);
        rhi.z = xhi.z + fmaxf(acc[oo][6] * a + bb, 0.f);
        rhi.w = xhi.w + fmaxf(acc[oo][7] * a + bb, 0.f);
        *(float4*)(out + off) = rlo;
        *(float4*)(out + off + 4) = rhi;
    }
}

// ---------------- launch ----------------
extern "C" void kernel_launch(void* const* d_in, const int* in_sizes, int n_in,
                              void* d_out, int out_size) {
    const float* x      = (const float*)d_in[0];
    const float* cs     = (const float*)d_in[1];
    const float* Wcsp   = (const float*)d_in[2];
    const float* Wx     = (const float*)d_in[3];
    const float* Wcs    = (const float*)d_in[4];
    const float* Wcv    = (const float*)d_in[5];
    const float* Wa     = (const float*)d_in[6];
    const float* Wcomb  = (const float*)d_in[7];
    const float* Wsing  = (const float*)d_in[8];
    const float* gamma  = (const float*)d_in[9];
    const float* beta   = (const float*)d_in[10];
    float* out = (float*)d_out;

    k_init<<<288, 256>>>(Wsing);
    k_space<<<dim3(144, 16), 256>>>(cs, Wcsp);
    k_g<<<(BB * HWSZ + 255) / 256, 256>>>(cs, Wcv, Wa, Wcomb);
    k_P<<<dim3(16, 8, 8), 128>>>(x);
    k_tok<<<dim3(8, 2, 8), 64>>>(Wx, Wcs);
    k_U<<<8, 256>>>();
    k_bnstats<<<dim3(12, 24, 8), 256>>>();
    k_bnfin<<<1, 64>>>(gamma, beta);
    k_final<<<dim3(12, 24, 8), 256>>>(x, out);
}